// round 9
// baseline (speedup 1.0000x reference)
#include <cuda_runtime.h>
#include <math.h>

// Round 9: R8 structure (16x8 tile, 256 thr, 2 blocks/SM) + w_in in
// __constant__ (transposed [k][ch]) so phase-A weight reads leave the
// shared-memory crossbar (uniform/constant port).

#define HALO   240     // 20 x 12
// smem float offsets
#define SM_SX     0        // 64*240 = 15360
#define SM_SPN    15360    // 2*240  = 480
#define SM_XC     15840    // 24*240 = 5760  (slots 0-11 A-half, 12-23 B-half)
#define SM_D3A    21600    // 4 cpl * 2 h * 180 = 1440
#define SM_GDW1   23040    // 4*2*27 = 216
#define SM_GDW3A  23256    // 216
#define SM_GDW3B  23472    // 72
#define SM_GWOUT  23544    // 4*64 = 256
#define SM_BDW1   23800    // 128
#define SM_BDW3A  23928    // 128
#define SM_BDW3B  24056    // 128
#define SM_BOUT   24184    // 64
#define SM_WPN    24248    // 256
#define SM_BPN    24504    // 128
#define SM_BIN    24632    // 256
#define SM_TOTAL  24888    // 99552 bytes -> 2 blocks/SM

// w_in transposed: c_winT[k*256 + c] = w_in[c*64 + k]   (64 KB exactly)
__constant__ float c_winT[64 * 256];
__device__ float g_winT[64 * 256];

__global__ void prep_winT(const float* __restrict__ w_in) {
    int i = blockIdx.x * 256 + threadIdx.x;   // 0..16383
    int k = i >> 8, c = i & 255;
    g_winT[k * 256 + c] = w_in[c * 64 + k];
}

__device__ __forceinline__ float gelu_exact(float v) {
    return 0.5f * v * (1.0f + erff(v * 0.70710678118654752f));
}

// Phase A for one halo pixel q. NA4 = # of float4 A-side xi groups {0,1,3}.
template<int NA4>
__device__ __forceinline__ void phaseA(float* sm, int g, int q, float m,
                                       float pnA, float pnB)
{
    float a[12 + 4 * NA4 + (NA4 == 0 ? 1 : 0)];   // B-half then A-xi
#pragma unroll
    for (int j = 0; j < 12; ++j) a[j] = sm[SM_BIN + 64 + 12 * g + j];
    if (NA4 == 1) {
#pragma unroll
        for (int j = 0; j < 4; ++j) a[12 + j] = sm[SM_BIN + j];
    } else if (NA4 == 3) {
#pragma unroll
        for (int j = 0; j < 12; ++j) a[12 + j] = sm[SM_BIN + 12 * g - 128 + j];
    }
    const int bcol = 64 + 12 * g;
    const int acol = (NA4 == 1) ? 0 : 12 * g - 128;
#pragma unroll 4
    for (int k = 0; k < 64; ++k) {
        float s0 = sm[SM_SX + k * 240 + q];
        const float* wk = c_winT + k * 256;
#pragma unroll
        for (int j = 0; j < 3; ++j) {
            float4 w = *(const float4*)(wk + bcol + 4 * j);
            a[4 * j]     = fmaf(w.x, s0, a[4 * j]);
            a[4 * j + 1] = fmaf(w.y, s0, a[4 * j + 1]);
            a[4 * j + 2] = fmaf(w.z, s0, a[4 * j + 2]);
            a[4 * j + 3] = fmaf(w.w, s0, a[4 * j + 3]);
        }
#pragma unroll
        for (int j = 0; j < NA4; ++j) {
            float4 w = *(const float4*)(wk + acol + 4 * j);
            a[12 + 4 * j]     = fmaf(w.x, s0, a[12 + 4 * j]);
            a[12 + 4 * j + 1] = fmaf(w.y, s0, a[12 + 4 * j + 1]);
            a[12 + 4 * j + 2] = fmaf(w.z, s0, a[12 + 4 * j + 2]);
            a[12 + 4 * j + 3] = fmaf(w.w, s0, a[12 + 4 * j + 3]);
        }
    }
    // B-half -> XC slots 12..23
#pragma unroll
    for (int s = 0; s < 12; ++s)
        sm[SM_XC + (12 + s) * 240 + q] = a[s] * m;
    // A-half -> XC slots 0..11 (pn or xi)
#pragma unroll
    for (int s = 0; s < 12; ++s) {
        float val;
        const bool isPN = (NA4 == 0) || (NA4 == 1 && s < 8);
        if (isPN) {
            int c = 12 * g + s;
            float w0 = sm[SM_WPN + 2 * c], w1 = sm[SM_WPN + 2 * c + 1];
            val = fmaf(w0, pnA, fmaf(w1, pnB, sm[SM_BPN + c]));
        } else if (NA4 == 1) {
            val = a[12 + s - 8];
        } else {
            val = a[12 + s];
        }
        sm[SM_XC + s * 240 + q] = val * m;
    }
}

__global__ void __launch_bounds__(256, 2)
ffn_fused_kernel(const float* __restrict__ x,
                 const float* __restrict__ pneff,
                 const float* __restrict__ b_in,
                 const float* __restrict__ w_pn,  const float* __restrict__ b_pn,
                 const float* __restrict__ w_dw1, const float* __restrict__ b_dw1,
                 const float* __restrict__ w_dw3a,const float* __restrict__ b_dw3a,
                 const float* __restrict__ w_dw3b,const float* __restrict__ b_dw3b,
                 const float* __restrict__ w_out, const float* __restrict__ b_out,
                 float* __restrict__ out)
{
    extern __shared__ float sm[];
    const int tid = threadIdx.x;
    const int bx0 = blockIdx.x * 16;
    const int by0 = blockIdx.y * 8;
    const int b   = blockIdx.z;

    // ---- stage static biases/small weights ----
    if (tid < 128) {
        sm[SM_BDW1 + tid]  = b_dw1[tid];
        sm[SM_BDW3A + tid] = b_dw3a[tid];
        sm[SM_BDW3B + tid] = b_dw3b[tid];
        sm[SM_BPN + tid]   = b_pn[tid];
    }
    if (tid < 64) sm[SM_BOUT + tid] = b_out[tid];
    sm[SM_WPN + tid] = w_pn[tid];
    sm[SM_BIN + tid] = b_in[tid];

    // ---- stage x tile (20x12 halo, 64 ch) + pn tile ----
    {
        const float* xb = x + (size_t)b * 64 * 65536;
        for (int v = tid; v < 64 * HALO; v += 256) {
            int c = v / HALO, p = v - c * HALO;
            int ry = p / 20, rx = p - ry * 20;
            int gy = by0 + ry - 2, gx = bx0 + rx - 2;
            float vv = 0.0f;
            if ((unsigned)gy < 256u && (unsigned)gx < 256u)
                vv = xb[(size_t)c * 65536 + gy * 256 + gx];
            sm[SM_SX + c * HALO + p] = vv;
        }
        const float* pnb = pneff + (size_t)b * 2 * 65536;
        for (int v = tid; v < 2 * HALO; v += 256) {
            int c = v / HALO, p = v - c * HALO;
            int ry = p / 20, rx = p - ry * 20;
            int gy = by0 + ry - 2, gx = bx0 + rx - 2;
            float vv = 0.0f;
            if ((unsigned)gy < 256u && (unsigned)gx < 256u)
                vv = pnb[(size_t)c * 65536 + gy * 256 + gx];
            sm[SM_SPN + c * HALO + p] = vv;
        }
    }
    __syncthreads();

    const bool doA = (tid < HALO);
    const int q = doA ? tid : 0;
    float m = 0.0f, pnA = 0.0f, pnB = 0.0f;
    if (doA) {
        int ry = q / 20, rx = q - ry * 20;
        m = ((unsigned)(by0 + ry - 2) < 256u && (unsigned)(bx0 + rx - 2) < 256u) ? 1.f : 0.f;
        pnA = sm[SM_SPN + q];
        pnB = sm[SM_SPN + HALO + q];
    }

    const int px   = tid & 127;      // output pixel within 16x8 tile
    const int gh   = tid >> 7;       // 0: B1 + o0..31 ; 1: B3 + o32..63
    const int tyl  = px >> 4;        // 0..7
    const int tx   = px & 15;
    const int warp = tid >> 5;       // 0..7
    const int lane = tid & 31;

    float acc[32];
#pragma unroll
    for (int i = 0; i < 32; ++i) acc[i] = 0.0f;

    for (int g = 0; g < 16; ++g) {
        // ---- stage per-group dwconv/proj weights ----
        {
            for (int v = tid; v < 216; v += 256) {
                int cc = v / 27, t = v - cc * 27;           // cc = cpl*2 + half
                int ch = 4 * g + (cc >> 1) + (cc & 1) * 64;
                sm[SM_GDW1 + v]  = w_dw1[ch * 27 + t];
                sm[SM_GDW3A + v] = w_dw3a[ch * 27 + t];
            }
            if (tid < 72) {
                int cc = tid / 9, t = tid - cc * 9;
                int ch = 4 * g + (cc >> 1) + (cc & 1) * 64;
                sm[SM_GDW3B + tid] = w_dw3b[ch * 9 + t];
            }
            {
                int cpl = tid >> 6, o = tid & 63;
                sm[SM_GWOUT + tid] = w_out[o * 64 + 4 * g + cpl];
            }
        }
        __syncthreads();   // weights ready; prev-group XC/D3A readers done

        // ---- Phase A ----
        if (doA) {
            if (g < 10)       phaseA<0>(sm, g, q, m, pnA, pnB);
            else if (g == 10) phaseA<1>(sm, g, q, m, pnA, pnB);
            else              phaseA<3>(sm, g, q, m, pnA, pnB);
        }
        __syncthreads();   // XC ready

        // ---- B2: warp = (cpl, h), 180 px each ----
        {
            const int cpl = warp >> 1, h = warp & 1;
            const int cp = 4 * g + cpl;
            float wr[27];
#pragma unroll
            for (int t = 0; t < 27; ++t) wr[t] = sm[SM_GDW3A + (cpl * 2 + h) * 27 + t];
            const float bias = sm[SM_BDW3A + cp + h * 64];
            const float* xb = sm + SM_XC + (h * 12 + 3 * cpl) * 240;
            float* dst = sm + SM_D3A + cpl * 360 + h * 180;
            for (int i = lane; i < 180; i += 32) {
                int qy = i / 18, qx = i - qy * 18;
                float d = bias;
#pragma unroll
                for (int j = 0; j < 3; ++j)
#pragma unroll
                    for (int ky = 0; ky < 3; ++ky)
#pragma unroll
                        for (int kx = 0; kx < 3; ++kx)
                            d = fmaf(wr[j * 9 + ky * 3 + kx],
                                     xb[j * 240 + (qy + ky) * 20 + qx + kx], d);
                int gy = by0 + qy - 1, gx = bx0 + qx - 1;
                bool ok = ((unsigned)gy < 256u) && ((unsigned)gx < 256u);
                dst[i] = ok ? d : 0.0f;
            }
        }
        __syncthreads();   // D3A ready

        if (gh == 0) {
            // ---- B1 + proj (o 0..31) ----
#pragma unroll
            for (int cpl = 0; cpl < 4; ++cpl) {
                const int cp = 4 * g + cpl;
                float d1a = sm[SM_BDW1 + cp];
                float d1b = sm[SM_BDW1 + cp + 64];
                const float* wA = sm + SM_GDW1 + cpl * 54;
                const float* wB = wA + 27;
                const float* xcA = sm + SM_XC + (3 * cpl) * 240;
                const float* xcB = sm + SM_XC + (12 + 3 * cpl) * 240;
#pragma unroll
                for (int j = 0; j < 3; ++j)
#pragma unroll
                    for (int ky = 0; ky < 3; ++ky)
#pragma unroll
                        for (int kx = 0; kx < 3; ++kx) {
                            int xi = (tyl + 1 + ky) * 20 + (tx + 1 + kx);
                            int t = j * 9 + ky * 3 + kx;
                            d1a = fmaf(wA[t], xcA[j * 240 + xi], d1a);
                            d1b = fmaf(wB[t], xcB[j * 240 + xi], d1b);
                        }
                float g1 = gelu_exact(d1a) * d1b;
                const float4* wo = (const float4*)(sm + SM_GWOUT + cpl * 64);
#pragma unroll
                for (int mm = 0; mm < 8; ++mm) {
                    float4 w = wo[mm];
                    acc[4 * mm]     = fmaf(w.x, g1, acc[4 * mm]);
                    acc[4 * mm + 1] = fmaf(w.y, g1, acc[4 * mm + 1]);
                    acc[4 * mm + 2] = fmaf(w.z, g1, acc[4 * mm + 2]);
                    acc[4 * mm + 3] = fmaf(w.w, g1, acc[4 * mm + 3]);
                }
            }
        } else {
            // ---- B3 + proj (o 32..63) ----
#pragma unroll
            for (int cpl = 0; cpl < 4; ++cpl) {
                const int cp = 4 * g + cpl;
                float dA = sm[SM_BDW3B + cp];
                float dB = sm[SM_BDW3B + cp + 64];
                const float* wA = sm + SM_GDW3B + cpl * 18;
                const float* wB = wA + 9;
                const float* dz = sm + SM_D3A + cpl * 360;
#pragma unroll
                for (int ky = 0; ky < 3; ++ky)
#pragma unroll
                    for (int kx = 0; kx < 3; ++kx) {
                        int qi = (tyl + ky) * 18 + (tx + kx);
                        int t = ky * 3 + kx;
                        dA = fmaf(wA[t], dz[qi], dA);
                        dB = fmaf(wB[t], dz[180 + qi], dB);
                    }
                float g2 = gelu_exact(dA) * dB;
                const float4* wo = (const float4*)(sm + SM_GWOUT + cpl * 64 + 32);
#pragma unroll
                for (int mm = 0; mm < 8; ++mm) {
                    float4 w = wo[mm];
                    acc[4 * mm]     = fmaf(w.x, g2, acc[4 * mm]);
                    acc[4 * mm + 1] = fmaf(w.y, g2, acc[4 * mm + 1]);
                    acc[4 * mm + 2] = fmaf(w.z, g2, acc[4 * mm + 2]);
                    acc[4 * mm + 3] = fmaf(w.w, g2, acc[4 * mm + 3]);
                }
            }
        }
        __syncthreads();   // protect GDW*/XC/D3A before next group's staging
    }

    // ---- write output: gh picks channel half ----
    float* ob = out + (size_t)b * 64 * 65536 + (size_t)(by0 + tyl) * 256 + (bx0 + tx);
    const int o0 = gh * 32;
#pragma unroll
    for (int i = 0; i < 32; ++i)
        ob[(size_t)(o0 + i) * 65536] = acc[i] + sm[SM_BOUT + o0 + i];
}

extern "C" void kernel_launch(void* const* d_in, const int* in_sizes, int n_in,
                              void* d_out, int out_size)
{
    (void)in_sizes; (void)n_in; (void)out_size;
    const float* x      = (const float*)d_in[0];
    const float* pneff  = (const float*)d_in[1];
    const float* w_in   = (const float*)d_in[2];
    float* out = (float*)d_out;

    prep_winT<<<64, 256>>>(w_in);
    void* p_winT = nullptr;
    cudaGetSymbolAddress(&p_winT, g_winT);
    cudaMemcpyToSymbolAsync(c_winT, p_winT, 64 * 256 * sizeof(float), 0,
                            cudaMemcpyDeviceToDevice, 0);

    const size_t smem_bytes = SM_TOTAL * sizeof(float);
    cudaFuncSetAttribute(ffn_fused_kernel,
                         cudaFuncAttributeMaxDynamicSharedMemorySize,
                         (int)smem_bytes);
    dim3 grid(16, 32, 4);
    ffn_fused_kernel<<<grid, 256, smem_bytes>>>(
        x, pneff,
        (const float*)d_in[3],
        (const float*)d_in[4],  (const float*)d_in[5],
        (const float*)d_in[6],  (const float*)d_in[7],
        (const float*)d_in[8],  (const float*)d_in[9],
        (const float*)d_in[10], (const float*)d_in[11],
        (const float*)d_in[12], (const float*)d_in[13],
        out);
}

// round 10
// speedup vs baseline: 1.6585x; 1.6585x over previous
#include <cuda_runtime.h>
#include <math.h>

// Round 10: R8 base (16x8 tile, 256 thr, 2 blocks/SM) +
//  (1) phase-A channel-split across warp halves, 2 px/thread
//  (2) B2 vertical sliding window with shuffles

#define HALO   240     // 20 x 12
// smem float offsets
#define SM_SX     0        // 64*240 = 15360
#define SM_SPN    15360    // 2*240  = 480
#define SM_XC     15840    // 24*240 = 5760  (slots 0-11 A-half, 12-23 B-half)
#define SM_D3A    21600    // 4 cpl * 2 h * 180 = 1440
#define SM_WT     23040    // 64*24  = 1536
#define SM_GDW1   24576    // 216
#define SM_GDW3A  24792    // 216
#define SM_GDW3B  25008    // 72
#define SM_GWOUT  25080    // 256
#define SM_BDW1   25336    // 128
#define SM_BDW3A  25464    // 128
#define SM_BDW3B  25592    // 128
#define SM_BOUT   25720    // 64
#define SM_WPN    25784    // 256
#define SM_BPN    26040    // 128
#define SM_BIN    26168    // 256
#define SM_TOTAL  26424    // 105696 bytes -> 2 blocks/SM

__device__ __forceinline__ float gelu_exact(float v) {
    return 0.5f * v * (1.0f + erff(v * 0.70710678118654752f));
}

// Phase A, B-half: 12 xi channels (xc 192+12g..203+12g), 2 px per thread.
__device__ __forceinline__ void phaseA_B(float* sm, int g, int q0, int q1,
                                         bool has2, float m0, float m1)
{
    float b0[12], b1[12];
#pragma unroll
    for (int j = 0; j < 12; ++j) {
        float bb = sm[SM_BIN + 64 + 12 * g + j];
        b0[j] = bb; b1[j] = bb;
    }
#pragma unroll 4
    for (int k = 0; k < 64; ++k) {
        float s0 = sm[SM_SX + k * 240 + q0];
        float s1 = sm[SM_SX + k * 240 + q1];
        const float* wt = sm + SM_WT + k * 24;
#pragma unroll
        for (int j = 0; j < 3; ++j) {
            float4 w = *(const float4*)(wt + 4 * j);
            b0[4 * j]     = fmaf(w.x, s0, b0[4 * j]);
            b0[4 * j + 1] = fmaf(w.y, s0, b0[4 * j + 1]);
            b0[4 * j + 2] = fmaf(w.z, s0, b0[4 * j + 2]);
            b0[4 * j + 3] = fmaf(w.w, s0, b0[4 * j + 3]);
            b1[4 * j]     = fmaf(w.x, s1, b1[4 * j]);
            b1[4 * j + 1] = fmaf(w.y, s1, b1[4 * j + 1]);
            b1[4 * j + 2] = fmaf(w.z, s1, b1[4 * j + 2]);
            b1[4 * j + 3] = fmaf(w.w, s1, b1[4 * j + 3]);
        }
    }
#pragma unroll
    for (int s = 0; s < 12; ++s) {
        sm[SM_XC + (12 + s) * 240 + q0] = b0[s] * m0;
        if (has2) sm[SM_XC + (12 + s) * 240 + q1] = b1[s] * m1;
    }
}

// Phase A, A-half: slots 0..11 = xc channels 12g..12g+11 (pn if <128, xi else),
// 2 px per thread. NA4 = # of float4 xi groups {0,1,3}.
template<int NA4>
__device__ __forceinline__ void phaseA_A(float* sm, int g, int q0, int q1,
                                         bool has2, float m0, float m1,
                                         float pnA0, float pnB0,
                                         float pnA1, float pnB1)
{
    float a0[4 * NA4 + (NA4 == 0 ? 1 : 0)];
    float a1[4 * NA4 + (NA4 == 0 ? 1 : 0)];
    if (NA4 == 1) {
#pragma unroll
        for (int j = 0; j < 4; ++j) {
            float bb = sm[SM_BIN + j];          // xi ch 0..3
            a0[j] = bb; a1[j] = bb;
        }
    } else if (NA4 == 3) {
#pragma unroll
        for (int j = 0; j < 12; ++j) {
            float bb = sm[SM_BIN + 12 * g - 128 + j];
            a0[j] = bb; a1[j] = bb;
        }
    }
    if (NA4 > 0) {
#pragma unroll 4
        for (int k = 0; k < 64; ++k) {
            float s0 = sm[SM_SX + k * 240 + q0];
            float s1 = sm[SM_SX + k * 240 + q1];
            const float* wt = sm + SM_WT + k * 24 + 12;
#pragma unroll
            for (int j = 0; j < NA4; ++j) {
                float4 w = *(const float4*)(wt + 4 * j);
                a0[4 * j]     = fmaf(w.x, s0, a0[4 * j]);
                a0[4 * j + 1] = fmaf(w.y, s0, a0[4 * j + 1]);
                a0[4 * j + 2] = fmaf(w.z, s0, a0[4 * j + 2]);
                a0[4 * j + 3] = fmaf(w.w, s0, a0[4 * j + 3]);
                a1[4 * j]     = fmaf(w.x, s1, a1[4 * j]);
                a1[4 * j + 1] = fmaf(w.y, s1, a1[4 * j + 1]);
                a1[4 * j + 2] = fmaf(w.z, s1, a1[4 * j + 2]);
                a1[4 * j + 3] = fmaf(w.w, s1, a1[4 * j + 3]);
            }
        }
    }
#pragma unroll
    for (int s = 0; s < 12; ++s) {
        const bool isPN = (NA4 == 0) || (NA4 == 1 && s < 8);
        float v0, v1;
        if (isPN) {
            int c = 12 * g + s;
            float w0 = sm[SM_WPN + 2 * c], w1 = sm[SM_WPN + 2 * c + 1];
            float bb = sm[SM_BPN + c];
            v0 = fmaf(w0, pnA0, fmaf(w1, pnB0, bb));
            v1 = fmaf(w0, pnA1, fmaf(w1, pnB1, bb));
        } else {
            int idx = (NA4 == 1) ? (s - 8) : s;
            v0 = a0[idx]; v1 = a1[idx];
        }
        sm[SM_XC + s * 240 + q0] = v0 * m0;
        if (has2) sm[SM_XC + s * 240 + q1] = v1 * m1;
    }
}

__global__ void __launch_bounds__(256, 2)
ffn_fused_kernel(const float* __restrict__ x,
                 const float* __restrict__ pneff,
                 const float* __restrict__ w_in,  const float* __restrict__ b_in,
                 const float* __restrict__ w_pn,  const float* __restrict__ b_pn,
                 const float* __restrict__ w_dw1, const float* __restrict__ b_dw1,
                 const float* __restrict__ w_dw3a,const float* __restrict__ b_dw3a,
                 const float* __restrict__ w_dw3b,const float* __restrict__ b_dw3b,
                 const float* __restrict__ w_out, const float* __restrict__ b_out,
                 float* __restrict__ out)
{
    extern __shared__ float sm[];
    const int tid = threadIdx.x;
    const int bx0 = blockIdx.x * 16;
    const int by0 = blockIdx.y * 8;
    const int b   = blockIdx.z;

    // ---- stage static biases/small weights ----
    if (tid < 128) {
        sm[SM_BDW1 + tid]  = b_dw1[tid];
        sm[SM_BDW3A + tid] = b_dw3a[tid];
        sm[SM_BDW3B + tid] = b_dw3b[tid];
        sm[SM_BPN + tid]   = b_pn[tid];
    }
    if (tid < 64) sm[SM_BOUT + tid] = b_out[tid];
    sm[SM_WPN + tid] = w_pn[tid];
    sm[SM_BIN + tid] = b_in[tid];

    // ---- stage x tile (20x12 halo, 64 ch) + pn tile ----
    {
        const float* xb = x + (size_t)b * 64 * 65536;
        for (int v = tid; v < 64 * HALO; v += 256) {
            int c = v / HALO, p = v - c * HALO;
            int ry = p / 20, rx = p - ry * 20;
            int gy = by0 + ry - 2, gx = bx0 + rx - 2;
            float vv = 0.0f;
            if ((unsigned)gy < 256u && (unsigned)gx < 256u)
                vv = xb[(size_t)c * 65536 + gy * 256 + gx];
            sm[SM_SX + c * HALO + p] = vv;
        }
        const float* pnb = pneff + (size_t)b * 2 * 65536;
        for (int v = tid; v < 2 * HALO; v += 256) {
            int c = v / HALO, p = v - c * HALO;
            int ry = p / 20, rx = p - ry * 20;
            int gy = by0 + ry - 2, gx = bx0 + rx - 2;
            float vv = 0.0f;
            if ((unsigned)gy < 256u && (unsigned)gx < 256u)
                vv = pnb[(size_t)c * 65536 + gy * 256 + gx];
            sm[SM_SPN + c * HALO + p] = vv;
        }
    }
    __syncthreads();

    // phase-A mapping: half = tid>>7 (0: B-half, 1: A-half); 2 px per thread
    const int tA  = tid & 127;
    const int gh  = tid >> 7;
    const int q0  = tA;
    const bool has2 = (tA < 112);
    const int q1  = has2 ? (tA + 128) : q0;
    float m0, m1;
    {
        int ry = q0 / 20, rx = q0 - ry * 20;
        m0 = ((unsigned)(by0 + ry - 2) < 256u && (unsigned)(bx0 + rx - 2) < 256u) ? 1.f : 0.f;
        int ry1 = q1 / 20, rx1 = q1 - ry1 * 20;
        m1 = (has2 && (unsigned)(by0 + ry1 - 2) < 256u && (unsigned)(bx0 + rx1 - 2) < 256u) ? 1.f : 0.f;
    }
    const float pnA0 = sm[SM_SPN + q0], pnB0 = sm[SM_SPN + HALO + q0];
    const float pnA1 = sm[SM_SPN + q1], pnB1 = sm[SM_SPN + HALO + q1];

    const int tyl  = tA >> 4;        // output row 0..7
    const int tx   = tA & 15;
    const int warp = tid >> 5;       // 0..7
    const int lane = tid & 31;

    float acc[32];
#pragma unroll
    for (int i = 0; i < 32; ++i) acc[i] = 0.0f;

    for (int g = 0; g < 16; ++g) {
        // ---- stage per-group weights ----
        {
            const int nw = (g < 10) ? 768 : (g == 10 ? 1024 : 1536);
            const int ncol = nw / 64;
            for (int v = tid; v < nw; v += 256) {
                int k = v / ncol, j = v - k * ncol;
                int xi = (j < 12) ? (64 + 12 * g + j)
                                  : ((g == 10) ? (j - 12) : (12 * g - 128 + j - 12));
                sm[SM_WT + k * 24 + j] = w_in[xi * 64 + k];
            }
            for (int v = tid; v < 216; v += 256) {
                int cc = v / 27, t = v - cc * 27;
                int ch = 4 * g + (cc >> 1) + (cc & 1) * 64;
                sm[SM_GDW1 + v]  = w_dw1[ch * 27 + t];
                sm[SM_GDW3A + v] = w_dw3a[ch * 27 + t];
            }
            if (tid < 72) {
                int cc = tid / 9, t = tid - cc * 9;
                int ch = 4 * g + (cc >> 1) + (cc & 1) * 64;
                sm[SM_GDW3B + tid] = w_dw3b[ch * 9 + t];
            }
            {
                int cpl = tid >> 6, o = tid & 63;
                sm[SM_GWOUT + tid] = w_out[o * 64 + 4 * g + cpl];
            }
        }
        __syncthreads();   // weights ready

        // ---- Phase A: channel-split ----
        if (gh == 0) {
            phaseA_B(sm, g, q0, q1, has2, m0, m1);
        } else {
            if (g < 10)       phaseA_A<0>(sm, g, q0, q1, has2, m0, m1, pnA0, pnB0, pnA1, pnB1);
            else if (g == 10) phaseA_A<1>(sm, g, q0, q1, has2, m0, m1, pnA0, pnB0, pnA1, pnB1);
            else              phaseA_A<3>(sm, g, q0, q1, has2, m0, m1, pnA0, pnB0, pnA1, pnB1);
        }
        __syncthreads();   // XC ready

        // ---- B2: warp = (cpl, h), vertical sliding window + shuffle ----
        {
            const int cpl = warp >> 1, h = warp & 1;
            const int cp = 4 * g + cpl;
            float wr[27];
#pragma unroll
            for (int t = 0; t < 27; ++t) wr[t] = sm[SM_GDW3A + (cpl * 2 + h) * 27 + t];
            const float bias = sm[SM_BDW3A + cp + h * 64];
            const float* xb = sm + SM_XC + (h * 12 + 3 * cpl) * 240;
            float* dst = sm + SM_D3A + cpl * 360 + h * 180;
            const bool ld  = (lane < 20);
            const bool stv = (lane < 18);
            const int gxc  = bx0 + lane - 1;
            const bool colOK = stv && ((unsigned)gxc < 256u);

            float v0[3], v1[3], v2[3], p0[3], p1[3], p2[3], r0[3], r1[3], r2[3];
#pragma unroll
            for (int j = 0; j < 3; ++j) {
                float a = ld ? xb[j * 240 + lane] : 0.0f;
                v0[j] = a;
                p0[j] = __shfl_down_sync(0xffffffffu, a, 1);
                r0[j] = __shfl_down_sync(0xffffffffu, a, 2);
                float bva = ld ? xb[j * 240 + 20 + lane] : 0.0f;
                v1[j] = bva;
                p1[j] = __shfl_down_sync(0xffffffffu, bva, 1);
                r1[j] = __shfl_down_sync(0xffffffffu, bva, 2);
            }
#pragma unroll
            for (int qy = 0; qy < 10; ++qy) {
#pragma unroll
                for (int j = 0; j < 3; ++j) {
                    float c = ld ? xb[j * 240 + (qy + 2) * 20 + lane] : 0.0f;
                    v2[j] = c;
                    p2[j] = __shfl_down_sync(0xffffffffu, c, 1);
                    r2[j] = __shfl_down_sync(0xffffffffu, c, 2);
                }
                float d = bias;
#pragma unroll
                for (int j = 0; j < 3; ++j) {
                    d = fmaf(wr[j * 9 + 0], v0[j], d);
                    d = fmaf(wr[j * 9 + 1], p0[j], d);
                    d = fmaf(wr[j * 9 + 2], r0[j], d);
                    d = fmaf(wr[j * 9 + 3], v1[j], d);
                    d = fmaf(wr[j * 9 + 4], p1[j], d);
                    d = fmaf(wr[j * 9 + 5], r1[j], d);
                    d = fmaf(wr[j * 9 + 6], v2[j], d);
                    d = fmaf(wr[j * 9 + 7], p2[j], d);
                    d = fmaf(wr[j * 9 + 8], r2[j], d);
                }
                if (stv) {
                    int gy = by0 + qy - 1;
                    bool ok = colOK && ((unsigned)gy < 256u);
                    dst[qy * 18 + lane] = ok ? d : 0.0f;
                }
#pragma unroll
                for (int j = 0; j < 3; ++j) {
                    v0[j] = v1[j]; p0[j] = p1[j]; r0[j] = r1[j];
                    v1[j] = v2[j]; p1[j] = p2[j]; r1[j] = r2[j];
                }
            }
        }
        __syncthreads();   // D3A ready

        if (gh == 0) {
            // ---- B1 + proj (o 0..31) ----
#pragma unroll
            for (int cpl = 0; cpl < 4; ++cpl) {
                const int cp = 4 * g + cpl;
                float d1a = sm[SM_BDW1 + cp];
                float d1b = sm[SM_BDW1 + cp + 64];
                const float* wA = sm + SM_GDW1 + cpl * 54;
                const float* wB = wA + 27;
                const float* xcA = sm + SM_XC + (3 * cpl) * 240;
                const float* xcB = sm + SM_XC + (12 + 3 * cpl) * 240;
#pragma unroll
                for (int j = 0; j < 3; ++j)
#pragma unroll
                    for (int ky = 0; ky < 3; ++ky)
#pragma unroll
                        for (int kx = 0; kx < 3; ++kx) {
                            int xi = (tyl + 1 + ky) * 20 + (tx + 1 + kx);
                            int t = j * 9 + ky * 3 + kx;
                            d1a = fmaf(wA[t], xcA[j * 240 + xi], d1a);
                            d1b = fmaf(wB[t], xcB[j * 240 + xi], d1b);
                        }
                float g1 = gelu_exact(d1a) * d1b;
                const float4* wo = (const float4*)(sm + SM_GWOUT + cpl * 64);
#pragma unroll
                for (int mm = 0; mm < 8; ++mm) {
                    float4 w = wo[mm];
                    acc[4 * mm]     = fmaf(w.x, g1, acc[4 * mm]);
                    acc[4 * mm + 1] = fmaf(w.y, g1, acc[4 * mm + 1]);
                    acc[4 * mm + 2] = fmaf(w.z, g1, acc[4 * mm + 2]);
                    acc[4 * mm + 3] = fmaf(w.w, g1, acc[4 * mm + 3]);
                }
            }
        } else {
            // ---- B3 + proj (o 32..63) ----
#pragma unroll
            for (int cpl = 0; cpl < 4; ++cpl) {
                const int cp = 4 * g + cpl;
                float dA = sm[SM_BDW3B + cp];
                float dB = sm[SM_BDW3B + cp + 64];
                const float* wA = sm + SM_GDW3B + cpl * 18;
                const float* wB = wA + 9;
                const float* dz = sm + SM_D3A + cpl * 360;
#pragma unroll
                for (int ky = 0; ky < 3; ++ky)
#pragma unroll
                    for (int kx = 0; kx < 3; ++kx) {
                        int qi = (tyl + ky) * 18 + (tx + kx);
                        int t = ky * 3 + kx;
                        dA = fmaf(wA[t], dz[qi], dA);
                        dB = fmaf(wB[t], dz[180 + qi], dB);
                    }
                float g2 = gelu_exact(dA) * dB;
                const float4* wo = (const float4*)(sm + SM_GWOUT + cpl * 64 + 32);
#pragma unroll
                for (int mm = 0; mm < 8; ++mm) {
                    float4 w = wo[mm];
                    acc[4 * mm]     = fmaf(w.x, g2, acc[4 * mm]);
                    acc[4 * mm + 1] = fmaf(w.y, g2, acc[4 * mm + 1]);
                    acc[4 * mm + 2] = fmaf(w.z, g2, acc[4 * mm + 2]);
                    acc[4 * mm + 3] = fmaf(w.w, g2, acc[4 * mm + 3]);
                }
            }
        }
        __syncthreads();   // protect WT/GDW*/XC/D3A before next staging
    }

    // ---- write output: gh picks channel half ----
    float* ob = out + (size_t)b * 64 * 65536 + (size_t)(by0 + tyl) * 256 + (bx0 + tx);
    const int o0 = gh * 32;
#pragma unroll
    for (int i = 0; i < 32; ++i)
        ob[(size_t)(o0 + i) * 65536] = acc[i] + sm[SM_BOUT + o0 + i];
}

extern "C" void kernel_launch(void* const* d_in, const int* in_sizes, int n_in,
                              void* d_out, int out_size)
{
    (void)in_sizes; (void)n_in; (void)out_size;
    const float* x      = (const float*)d_in[0];
    const float* pneff  = (const float*)d_in[1];
    const float* w_in   = (const float*)d_in[2];
    const float* b_in   = (const float*)d_in[3];
    const float* w_pn   = (const float*)d_in[4];
    const float* b_pn   = (const float*)d_in[5];
    const float* w_dw1  = (const float*)d_in[6];
    const float* b_dw1  = (const float*)d_in[7];
    const float* w_dw3a = (const float*)d_in[8];
    const float* b_dw3a = (const float*)d_in[9];
    const float* w_dw3b = (const float*)d_in[10];
    const float* b_dw3b = (const float*)d_in[11];
    const float* w_out  = (const float*)d_in[12];
    const float* b_out  = (const float*)d_in[13];
    float* out = (float*)d_out;

    const size_t smem_bytes = SM_TOTAL * sizeof(float);
    cudaFuncSetAttribute(ffn_fused_kernel,
                         cudaFuncAttributeMaxDynamicSharedMemorySize,
                         (int)smem_bytes);
    dim3 grid(16, 32, 4);
    ffn_fused_kernel<<<grid, 256, smem_bytes>>>(
        x, pneff, w_in, b_in, w_pn, b_pn, w_dw1, b_dw1,
        w_dw3a, b_dw3a, w_dw3b, b_dw3b, w_out, b_out, out);
}

// round 11
// speedup vs baseline: 1.8361x; 1.1071x over previous
#include <cuda_runtime.h>
#include <math.h>

// Round 11: R10 base + B1 warp-specialized sliding window (B2 pattern),
// float4 weight preloads in B2/B3, raw-d1 smem handoff for gating.

#define HALO   240     // 20 x 12
// smem float offsets
#define SM_SX     0        // 64*240 = 15360
#define SM_SPN    15360    // 2*240  = 480
#define SM_XC     15840    // 24*240 = 5760
#define SM_D3A    21600    // 4*2*180 = 1440
#define SM_D1     23040    // 8 cc * 128 = 1024
#define SM_WT     24064    // 64*24 = 1536
#define SM_GDW1   25600    // 8*28 = 224 (padded)
#define SM_GDW3A  25824    // 8*28 = 224 (padded)
#define SM_GDW3B  26048    // 8*12 = 96  (padded)
#define SM_GWOUT  26144    // 4*64 = 256
#define SM_BDW1   26400    // 128
#define SM_BDW3A  26528    // 128
#define SM_BDW3B  26656    // 128
#define SM_BOUT   26784    // 64
#define SM_WPN    26848    // 256
#define SM_BPN    27104    // 128
#define SM_BIN    27232    // 256
#define SM_TOTAL  27488    // 109952 bytes -> 2 blocks/SM

__device__ __forceinline__ float gelu_exact(float v) {
    return 0.5f * v * (1.0f + erff(v * 0.70710678118654752f));
}

// ---- Phase A halves (unchanged from R10) ----
__device__ __forceinline__ void phaseA_B(float* sm, int g, int q0, int q1,
                                         bool has2, float m0, float m1)
{
    float b0[12], b1[12];
#pragma unroll
    for (int j = 0; j < 12; ++j) {
        float bb = sm[SM_BIN + 64 + 12 * g + j];
        b0[j] = bb; b1[j] = bb;
    }
#pragma unroll 4
    for (int k = 0; k < 64; ++k) {
        float s0 = sm[SM_SX + k * 240 + q0];
        float s1 = sm[SM_SX + k * 240 + q1];
        const float* wt = sm + SM_WT + k * 24;
#pragma unroll
        for (int j = 0; j < 3; ++j) {
            float4 w = *(const float4*)(wt + 4 * j);
            b0[4 * j]     = fmaf(w.x, s0, b0[4 * j]);
            b0[4 * j + 1] = fmaf(w.y, s0, b0[4 * j + 1]);
            b0[4 * j + 2] = fmaf(w.z, s0, b0[4 * j + 2]);
            b0[4 * j + 3] = fmaf(w.w, s0, b0[4 * j + 3]);
            b1[4 * j]     = fmaf(w.x, s1, b1[4 * j]);
            b1[4 * j + 1] = fmaf(w.y, s1, b1[4 * j + 1]);
            b1[4 * j + 2] = fmaf(w.z, s1, b1[4 * j + 2]);
            b1[4 * j + 3] = fmaf(w.w, s1, b1[4 * j + 3]);
        }
    }
#pragma unroll
    for (int s = 0; s < 12; ++s) {
        sm[SM_XC + (12 + s) * 240 + q0] = b0[s] * m0;
        if (has2) sm[SM_XC + (12 + s) * 240 + q1] = b1[s] * m1;
    }
}

template<int NA4>
__device__ __forceinline__ void phaseA_A(float* sm, int g, int q0, int q1,
                                         bool has2, float m0, float m1,
                                         float pnA0, float pnB0,
                                         float pnA1, float pnB1)
{
    float a0[4 * NA4 + (NA4 == 0 ? 1 : 0)];
    float a1[4 * NA4 + (NA4 == 0 ? 1 : 0)];
    if (NA4 == 1) {
#pragma unroll
        for (int j = 0; j < 4; ++j) {
            float bb = sm[SM_BIN + j];
            a0[j] = bb; a1[j] = bb;
        }
    } else if (NA4 == 3) {
#pragma unroll
        for (int j = 0; j < 12; ++j) {
            float bb = sm[SM_BIN + 12 * g - 128 + j];
            a0[j] = bb; a1[j] = bb;
        }
    }
    if (NA4 > 0) {
#pragma unroll 4
        for (int k = 0; k < 64; ++k) {
            float s0 = sm[SM_SX + k * 240 + q0];
            float s1 = sm[SM_SX + k * 240 + q1];
            const float* wt = sm + SM_WT + k * 24 + 12;
#pragma unroll
            for (int j = 0; j < NA4; ++j) {
                float4 w = *(const float4*)(wt + 4 * j);
                a0[4 * j]     = fmaf(w.x, s0, a0[4 * j]);
                a0[4 * j + 1] = fmaf(w.y, s0, a0[4 * j + 1]);
                a0[4 * j + 2] = fmaf(w.z, s0, a0[4 * j + 2]);
                a0[4 * j + 3] = fmaf(w.w, s0, a0[4 * j + 3]);
                a1[4 * j]     = fmaf(w.x, s1, a1[4 * j]);
                a1[4 * j + 1] = fmaf(w.y, s1, a1[4 * j + 1]);
                a1[4 * j + 2] = fmaf(w.z, s1, a1[4 * j + 2]);
                a1[4 * j + 3] = fmaf(w.w, s1, a1[4 * j + 3]);
            }
        }
    }
#pragma unroll
    for (int s = 0; s < 12; ++s) {
        const bool isPN = (NA4 == 0) || (NA4 == 1 && s < 8);
        float v0, v1;
        if (isPN) {
            int c = 12 * g + s;
            float w0 = sm[SM_WPN + 2 * c], w1 = sm[SM_WPN + 2 * c + 1];
            float bb = sm[SM_BPN + c];
            v0 = fmaf(w0, pnA0, fmaf(w1, pnB0, bb));
            v1 = fmaf(w0, pnA1, fmaf(w1, pnB1, bb));
        } else {
            int idx = (NA4 == 1) ? (s - 8) : s;
            v0 = a0[idx]; v1 = a1[idx];
        }
        sm[SM_XC + s * 240 + q0] = v0 * m0;
        if (has2) sm[SM_XC + s * 240 + q1] = v1 * m1;
    }
}

__global__ void __launch_bounds__(256, 2)
ffn_fused_kernel(const float* __restrict__ x,
                 const float* __restrict__ pneff,
                 const float* __restrict__ w_in,  const float* __restrict__ b_in,
                 const float* __restrict__ w_pn,  const float* __restrict__ b_pn,
                 const float* __restrict__ w_dw1, const float* __restrict__ b_dw1,
                 const float* __restrict__ w_dw3a,const float* __restrict__ b_dw3a,
                 const float* __restrict__ w_dw3b,const float* __restrict__ b_dw3b,
                 const float* __restrict__ w_out, const float* __restrict__ b_out,
                 float* __restrict__ out)
{
    extern __shared__ float sm[];
    const int tid = threadIdx.x;
    const int bx0 = blockIdx.x * 16;
    const int by0 = blockIdx.y * 8;
    const int b   = blockIdx.z;

    if (tid < 128) {
        sm[SM_BDW1 + tid]  = b_dw1[tid];
        sm[SM_BDW3A + tid] = b_dw3a[tid];
        sm[SM_BDW3B + tid] = b_dw3b[tid];
        sm[SM_BPN + tid]   = b_pn[tid];
    }
    if (tid < 64) sm[SM_BOUT + tid] = b_out[tid];
    sm[SM_WPN + tid] = w_pn[tid];
    sm[SM_BIN + tid] = b_in[tid];

    {
        const float* xb = x + (size_t)b * 64 * 65536;
        for (int v = tid; v < 64 * HALO; v += 256) {
            int c = v / HALO, p = v - c * HALO;
            int ry = p / 20, rx = p - ry * 20;
            int gy = by0 + ry - 2, gx = bx0 + rx - 2;
            float vv = 0.0f;
            if ((unsigned)gy < 256u && (unsigned)gx < 256u)
                vv = xb[(size_t)c * 65536 + gy * 256 + gx];
            sm[SM_SX + c * HALO + p] = vv;
        }
        const float* pnb = pneff + (size_t)b * 2 * 65536;
        for (int v = tid; v < 2 * HALO; v += 256) {
            int c = v / HALO, p = v - c * HALO;
            int ry = p / 20, rx = p - ry * 20;
            int gy = by0 + ry - 2, gx = bx0 + rx - 2;
            float vv = 0.0f;
            if ((unsigned)gy < 256u && (unsigned)gx < 256u)
                vv = pnb[(size_t)c * 65536 + gy * 256 + gx];
            sm[SM_SPN + c * HALO + p] = vv;
        }
    }
    __syncthreads();

    const int tA  = tid & 127;
    const int gh  = tid >> 7;
    const int q0  = tA;
    const bool has2 = (tA < 112);
    const int q1  = has2 ? (tA + 128) : q0;
    float m0, m1;
    {
        int ry = q0 / 20, rx = q0 - ry * 20;
        m0 = ((unsigned)(by0 + ry - 2) < 256u && (unsigned)(bx0 + rx - 2) < 256u) ? 1.f : 0.f;
        int ry1 = q1 / 20, rx1 = q1 - ry1 * 20;
        m1 = (has2 && (unsigned)(by0 + ry1 - 2) < 256u && (unsigned)(bx0 + rx1 - 2) < 256u) ? 1.f : 0.f;
    }
    const float pnA0 = sm[SM_SPN + q0], pnB0 = sm[SM_SPN + HALO + q0];
    const float pnA1 = sm[SM_SPN + q1], pnB1 = sm[SM_SPN + HALO + q1];

    const int tyl  = tA >> 4;
    const int tx   = tA & 15;
    const int warp = tid >> 5;
    const int lane = tid & 31;

    float acc[32];
#pragma unroll
    for (int i = 0; i < 32; ++i) acc[i] = 0.0f;

    for (int g = 0; g < 16; ++g) {
        // ---- stage per-group weights ----
        {
            const int nw = (g < 10) ? 768 : (g == 10 ? 1024 : 1536);
            const int ncol = nw / 64;
            for (int v = tid; v < nw; v += 256) {
                int k = v / ncol, j = v - k * ncol;
                int xi = (j < 12) ? (64 + 12 * g + j)
                                  : ((g == 10) ? (j - 12) : (12 * g - 128 + j - 12));
                sm[SM_WT + k * 24 + j] = w_in[xi * 64 + k];
            }
            for (int v = tid; v < 216; v += 256) {
                int cc = v / 27, t = v - cc * 27;
                int ch = 4 * g + (cc >> 1) + (cc & 1) * 64;
                sm[SM_GDW1 + cc * 28 + t]  = w_dw1[ch * 27 + t];
                sm[SM_GDW3A + cc * 28 + t] = w_dw3a[ch * 27 + t];
            }
            if (tid < 72) {
                int cc = tid / 9, t = tid - cc * 9;
                int ch = 4 * g + (cc >> 1) + (cc & 1) * 64;
                sm[SM_GDW3B + cc * 12 + t] = w_dw3b[ch * 9 + t];
            }
            {
                int cpl = tid >> 6, o = tid & 63;
                sm[SM_GWOUT + tid] = w_out[o * 64 + 4 * g + cpl];
            }
        }
        __syncthreads();   // weights ready

        // ---- Phase A (channel-split) ----
        if (gh == 0) {
            phaseA_B(sm, g, q0, q1, has2, m0, m1);
        } else {
            if (g < 10)       phaseA_A<0>(sm, g, q0, q1, has2, m0, m1, pnA0, pnB0, pnA1, pnB1);
            else if (g == 10) phaseA_A<1>(sm, g, q0, q1, has2, m0, m1, pnA0, pnB0, pnA1, pnB1);
            else              phaseA_A<3>(sm, g, q0, q1, has2, m0, m1, pnA0, pnB0, pnA1, pnB1);
        }
        __syncthreads();   // XC ready

        // ---- B1: warp = (cpl, chain), sliding window, raw d1 -> SM_D1 ----
        {
            const int cpl = warp >> 1, ch = warp & 1;
            const int cc = cpl * 2 + ch;
            float wr[28];
#pragma unroll
            for (int i = 0; i < 7; ++i) {
                float4 w4 = ((const float4*)(sm + SM_GDW1 + cc * 28))[i];
                wr[4 * i] = w4.x; wr[4 * i + 1] = w4.y;
                wr[4 * i + 2] = w4.z; wr[4 * i + 3] = w4.w;
            }
            const float bias = sm[SM_BDW1 + 4 * g + cpl + ch * 64];
            const float* xb = sm + SM_XC + (ch * 12 + 3 * cpl) * 240;
            float* dst = sm + SM_D1 + cc * 128;
            const bool ld = (lane < 18);
            float a0v[3], a1v[3], a2v[3], b0v[3], b1v[3], b2v[3], c0v[3], c1v[3], c2v[3];
#pragma unroll
            for (int j = 0; j < 3; ++j) {
                float v = ld ? xb[j * 240 + 20 + lane + 1] : 0.f;        // row 1
                a0v[j] = v;
                a1v[j] = __shfl_down_sync(0xffffffffu, v, 1);
                a2v[j] = __shfl_down_sync(0xffffffffu, v, 2);
                float w = ld ? xb[j * 240 + 40 + lane + 1] : 0.f;        // row 2
                b0v[j] = w;
                b1v[j] = __shfl_down_sync(0xffffffffu, w, 1);
                b2v[j] = __shfl_down_sync(0xffffffffu, w, 2);
            }
#pragma unroll
            for (int r = 0; r < 8; ++r) {
#pragma unroll
                for (int j = 0; j < 3; ++j) {
                    float v = ld ? xb[j * 240 + (r + 3) * 20 + lane + 1] : 0.f;
                    c0v[j] = v;
                    c1v[j] = __shfl_down_sync(0xffffffffu, v, 1);
                    c2v[j] = __shfl_down_sync(0xffffffffu, v, 2);
                }
                float d = bias;
#pragma unroll
                for (int j = 0; j < 3; ++j) {
                    d = fmaf(wr[j * 9 + 0], a0v[j], d);
                    d = fmaf(wr[j * 9 + 1], a1v[j], d);
                    d = fmaf(wr[j * 9 + 2], a2v[j], d);
                    d = fmaf(wr[j * 9 + 3], b0v[j], d);
                    d = fmaf(wr[j * 9 + 4], b1v[j], d);
                    d = fmaf(wr[j * 9 + 5], b2v[j], d);
                    d = fmaf(wr[j * 9 + 6], c0v[j], d);
                    d = fmaf(wr[j * 9 + 7], c1v[j], d);
                    d = fmaf(wr[j * 9 + 8], c2v[j], d);
                }
                if (lane < 16) dst[r * 16 + lane] = d;
#pragma unroll
                for (int j = 0; j < 3; ++j) {
                    a0v[j] = b0v[j]; a1v[j] = b1v[j]; a2v[j] = b2v[j];
                    b0v[j] = c0v[j]; b1v[j] = c1v[j]; b2v[j] = c2v[j];
                }
            }
        }

        // ---- B2: warp = (cpl, h), sliding window (R10) + float4 weights ----
        {
            const int cpl = warp >> 1, h = warp & 1;
            const int cc = cpl * 2 + h;
            const int cp = 4 * g + cpl;
            float wr[28];
#pragma unroll
            for (int i = 0; i < 7; ++i) {
                float4 w4 = ((const float4*)(sm + SM_GDW3A + cc * 28))[i];
                wr[4 * i] = w4.x; wr[4 * i + 1] = w4.y;
                wr[4 * i + 2] = w4.z; wr[4 * i + 3] = w4.w;
            }
            const float bias = sm[SM_BDW3A + cp + h * 64];
            const float* xb = sm + SM_XC + (h * 12 + 3 * cpl) * 240;
            float* dst = sm + SM_D3A + cpl * 360 + h * 180;
            const bool ld  = (lane < 20);
            const bool stv = (lane < 18);
            const int gxc  = bx0 + lane - 1;
            const bool colOK = stv && ((unsigned)gxc < 256u);

            float v0[3], v1[3], v2[3], p0[3], p1[3], p2[3], r0[3], r1[3], r2[3];
#pragma unroll
            for (int j = 0; j < 3; ++j) {
                float a = ld ? xb[j * 240 + lane] : 0.0f;
                v0[j] = a;
                p0[j] = __shfl_down_sync(0xffffffffu, a, 1);
                r0[j] = __shfl_down_sync(0xffffffffu, a, 2);
                float bva = ld ? xb[j * 240 + 20 + lane] : 0.0f;
                v1[j] = bva;
                p1[j] = __shfl_down_sync(0xffffffffu, bva, 1);
                r1[j] = __shfl_down_sync(0xffffffffu, bva, 2);
            }
#pragma unroll
            for (int qy = 0; qy < 10; ++qy) {
#pragma unroll
                for (int j = 0; j < 3; ++j) {
                    float c = ld ? xb[j * 240 + (qy + 2) * 20 + lane] : 0.0f;
                    v2[j] = c;
                    p2[j] = __shfl_down_sync(0xffffffffu, c, 1);
                    r2[j] = __shfl_down_sync(0xffffffffu, c, 2);
                }
                float d = bias;
#pragma unroll
                for (int j = 0; j < 3; ++j) {
                    d = fmaf(wr[j * 9 + 0], v0[j], d);
                    d = fmaf(wr[j * 9 + 1], p0[j], d);
                    d = fmaf(wr[j * 9 + 2], r0[j], d);
                    d = fmaf(wr[j * 9 + 3], v1[j], d);
                    d = fmaf(wr[j * 9 + 4], p1[j], d);
                    d = fmaf(wr[j * 9 + 5], r1[j], d);
                    d = fmaf(wr[j * 9 + 6], v2[j], d);
                    d = fmaf(wr[j * 9 + 7], p2[j], d);
                    d = fmaf(wr[j * 9 + 8], r2[j], d);
                }
                if (stv) {
                    int gy = by0 + qy - 1;
                    bool ok = colOK && ((unsigned)gy < 256u);
                    dst[qy * 18 + lane] = ok ? d : 0.0f;
                }
#pragma unroll
                for (int j = 0; j < 3; ++j) {
                    v0[j] = v1[j]; p0[j] = p1[j]; r0[j] = r1[j];
                    v1[j] = v2[j]; p1[j] = p2[j]; r1[j] = r2[j];
                }
            }
        }
        __syncthreads();   // D1 + D3A ready

        if (gh == 0) {
            // ---- gating + proj (o 0..31) from D1 ----
#pragma unroll
            for (int cpl = 0; cpl < 4; ++cpl) {
                float d1a = sm[SM_D1 + (cpl * 2 + 0) * 128 + tA];
                float d1b = sm[SM_D1 + (cpl * 2 + 1) * 128 + tA];
                float g1 = gelu_exact(d1a) * d1b;
                const float4* wo = (const float4*)(sm + SM_GWOUT + cpl * 64);
#pragma unroll
                for (int mm = 0; mm < 8; ++mm) {
                    float4 w = wo[mm];
                    acc[4 * mm]     = fmaf(w.x, g1, acc[4 * mm]);
                    acc[4 * mm + 1] = fmaf(w.y, g1, acc[4 * mm + 1]);
                    acc[4 * mm + 2] = fmaf(w.z, g1, acc[4 * mm + 2]);
                    acc[4 * mm + 3] = fmaf(w.w, g1, acc[4 * mm + 3]);
                }
            }
        } else {
            // ---- B3 + proj (o 32..63), float4 weight preload ----
#pragma unroll
            for (int cpl = 0; cpl < 4; ++cpl) {
                const int cp = 4 * g + cpl;
                float wA[12], wB[12];
#pragma unroll
                for (int i = 0; i < 3; ++i) {
                    float4 w4 = ((const float4*)(sm + SM_GDW3B + (cpl * 2) * 12))[i];
                    wA[4 * i] = w4.x; wA[4 * i + 1] = w4.y;
                    wA[4 * i + 2] = w4.z; wA[4 * i + 3] = w4.w;
                    float4 v4 = ((const float4*)(sm + SM_GDW3B + (cpl * 2 + 1) * 12))[i];
                    wB[4 * i] = v4.x; wB[4 * i + 1] = v4.y;
                    wB[4 * i + 2] = v4.z; wB[4 * i + 3] = v4.w;
                }
                float dA = sm[SM_BDW3B + cp];
                float dB = sm[SM_BDW3B + cp + 64];
                const float* dz = sm + SM_D3A + cpl * 360;
#pragma unroll
                for (int ky = 0; ky < 3; ++ky)
#pragma unroll
                    for (int kx = 0; kx < 3; ++kx) {
                        int qi = (tyl + ky) * 18 + (tx + kx);
                        int t = ky * 3 + kx;
                        dA = fmaf(wA[t], dz[qi], dA);
                        dB = fmaf(wB[t], dz[180 + qi], dB);
                    }
                float g2 = gelu_exact(dA) * dB;
                const float4* wo = (const float4*)(sm + SM_GWOUT + cpl * 64 + 32);
#pragma unroll
                for (int mm = 0; mm < 8; ++mm) {
                    float4 w = wo[mm];
                    acc[4 * mm]     = fmaf(w.x, g2, acc[4 * mm]);
                    acc[4 * mm + 1] = fmaf(w.y, g2, acc[4 * mm + 1]);
                    acc[4 * mm + 2] = fmaf(w.z, g2, acc[4 * mm + 2]);
                    acc[4 * mm + 3] = fmaf(w.w, g2, acc[4 * mm + 3]);
                }
            }
        }
        __syncthreads();   // protect WT/GDW*/XC/D1/D3A before next staging
    }

    float* ob = out + (size_t)b * 64 * 65536 + (size_t)(by0 + tyl) * 256 + (bx0 + tx);
    const int o0 = gh * 32;
#pragma unroll
    for (int i = 0; i < 32; ++i)
        ob[(size_t)(o0 + i) * 65536] = acc[i] + sm[SM_BOUT + o0 + i];
}

extern "C" void kernel_launch(void* const* d_in, const int* in_sizes, int n_in,
                              void* d_out, int out_size)
{
    (void)in_sizes; (void)n_in; (void)out_size;
    const float* x      = (const float*)d_in[0];
    const float* pneff  = (const float*)d_in[1];
    const float* w_in   = (const float*)d_in[2];
    const float* b_in   = (const float*)d_in[3];
    const float* w_pn   = (const float*)d_in[4];
    const float* b_pn   = (const float*)d_in[5];
    const float* w_dw1  = (const float*)d_in[6];
    const float* b_dw1  = (const float*)d_in[7];
    const float* w_dw3a = (const float*)d_in[8];
    const float* b_dw3a = (const float*)d_in[9];
    const float* w_dw3b = (const float*)d_in[10];
    const float* b_dw3b = (const float*)d_in[11];
    const float* w_out  = (const float*)d_in[12];
    const float* b_out  = (const float*)d_in[13];
    float* out = (float*)d_out;

    const size_t smem_bytes = SM_TOTAL * sizeof(float);
    cudaFuncSetAttribute(ffn_fused_kernel,
                         cudaFuncAttributeMaxDynamicSharedMemorySize,
                         (int)smem_bytes);
    dim3 grid(16, 32, 4);
    ffn_fused_kernel<<<grid, 256, smem_bytes>>>(
        x, pneff, w_in, b_in, w_pn, b_pn, w_dw1, b_dw1,
        w_dw3a, b_dw3a, w_dw3b, b_dw3b, w_out, b_out, out);
}

// round 12
// speedup vs baseline: 1.8767x; 1.0221x over previous
#include <cuda_runtime.h>
#include <math.h>

typedef unsigned long long u64;

// Round 12: R11 base + f32x2 packing in phase A (adjacent-pixel pairs,
// channel-paired accumulators) and in both projections.

#define HALO   240     // 20 x 12
// smem float offsets
#define SM_SX     0        // 64*240 = 15360
#define SM_SPN    15360    // 2*240  = 480
#define SM_XC     15840    // 24*240 = 5760
#define SM_D3A    21600    // 4*2*180 = 1440
#define SM_D1     23040    // 8 cc * 128 = 1024
#define SM_WT     24064    // 64*24 = 1536
#define SM_GDW1   25600    // 8*28 = 224 (padded)
#define SM_GDW3A  25824    // 8*28 = 224 (padded)
#define SM_GDW3B  26048    // 8*12 = 96  (padded)
#define SM_GWOUT  26144    // 4*64 = 256
#define SM_BDW1   26400    // 128
#define SM_BDW3A  26528    // 128
#define SM_BDW3B  26656    // 128
#define SM_BOUT   26784    // 64
#define SM_WPN    26848    // 256
#define SM_BPN    27104    // 128
#define SM_BIN    27232    // 256
#define SM_TOTAL  27488    // 109952 bytes -> 2 blocks/SM

__device__ __forceinline__ u64 pk2(float lo, float hi) {
    u64 r; asm("mov.b64 %0,{%1,%2};" : "=l"(r) : "f"(lo), "f"(hi)); return r;
}
__device__ __forceinline__ void upk2(u64 v, float& lo, float& hi) {
    asm("mov.b64 {%0,%1},%2;" : "=f"(lo), "=f"(hi) : "l"(v));
}
__device__ __forceinline__ void fma2(u64& d, u64 a, u64 b) {
    asm("fma.rn.f32x2 %0,%1,%2,%0;" : "+l"(d) : "l"(a), "l"(b));
}
__device__ __forceinline__ u64 lds64(const float* p) { return *(const u64*)p; }

__device__ __forceinline__ float gelu_exact(float v) {
    return 0.5f * v * (1.0f + erff(v * 0.70710678118654752f));
}

// Phase A, B-half: 12 xi channels (6 pairs) for adjacent pixels p0, p0+1.
__device__ __forceinline__ void phaseA_B(float* sm, int g, int p0,
                                         float m0, float m1)
{
    u64 a0[6], a1[6];
#pragma unroll
    for (int j = 0; j < 6; ++j) {
        u64 bp = lds64(sm + SM_BIN + 64 + 12 * g + 2 * j);
        a0[j] = bp; a1[j] = bp;
    }
#pragma unroll 4
    for (int k = 0; k < 64; ++k) {
        float2 s = *(const float2*)(sm + SM_SX + k * 240 + p0);
        u64 s0 = pk2(s.x, s.x);
        u64 s1 = pk2(s.y, s.y);
        const float* wt = sm + SM_WT + k * 24;
        ulonglong2 w01 = *(const ulonglong2*)(wt);
        ulonglong2 w23 = *(const ulonglong2*)(wt + 4);
        ulonglong2 w45 = *(const ulonglong2*)(wt + 8);
        fma2(a0[0], w01.x, s0); fma2(a1[0], w01.x, s1);
        fma2(a0[1], w01.y, s0); fma2(a1[1], w01.y, s1);
        fma2(a0[2], w23.x, s0); fma2(a1[2], w23.x, s1);
        fma2(a0[3], w23.y, s0); fma2(a1[3], w23.y, s1);
        fma2(a0[4], w45.x, s0); fma2(a1[4], w45.x, s1);
        fma2(a0[5], w45.y, s0); fma2(a1[5], w45.y, s1);
    }
#pragma unroll
    for (int j = 0; j < 6; ++j) {
        float lo0, hi0, lo1, hi1;
        upk2(a0[j], lo0, hi0);
        upk2(a1[j], lo1, hi1);
        float* c0 = sm + SM_XC + (12 + 2 * j) * 240 + p0;
        float* c1 = sm + SM_XC + (13 + 2 * j) * 240 + p0;
        c0[0] = lo0 * m0; c0[1] = lo1 * m1;
        c1[0] = hi0 * m0; c1[1] = hi1 * m1;
    }
}

// Phase A, A-half: slots 0..11 (pn if channel<128, xi else), pixels p0,p0+1.
// NP = # of xi channel pairs {0, 2, 6}.
template<int NP>
__device__ __forceinline__ void phaseA_A(float* sm, int g, int p0,
                                         float m0, float m1,
                                         float pn00, float pn01,
                                         float pn10, float pn11)
{
    float xv0[12], xv1[12];
    if (NP > 0) {
        u64 a0[NP > 0 ? NP : 1], a1[NP > 0 ? NP : 1];
        const int base = (NP == 2) ? 0 : (12 * g - 128);
#pragma unroll
        for (int j = 0; j < NP; ++j) {
            u64 bp = lds64(sm + SM_BIN + base + 2 * j);
            a0[j] = bp; a1[j] = bp;
        }
#pragma unroll 4
        for (int k = 0; k < 64; ++k) {
            float2 s = *(const float2*)(sm + SM_SX + k * 240 + p0);
            u64 s0 = pk2(s.x, s.x);
            u64 s1 = pk2(s.y, s.y);
            const float* wt = sm + SM_WT + k * 24 + 12;
            if (NP == 2) {
                ulonglong2 w = *(const ulonglong2*)(wt);
                fma2(a0[0], w.x, s0); fma2(a1[0], w.x, s1);
                fma2(a0[1], w.y, s0); fma2(a1[1], w.y, s1);
            } else {
                ulonglong2 w01 = *(const ulonglong2*)(wt);
                ulonglong2 w23 = *(const ulonglong2*)(wt + 4);
                ulonglong2 w45 = *(const ulonglong2*)(wt + 8);
                fma2(a0[0], w01.x, s0); fma2(a1[0], w01.x, s1);
                fma2(a0[1], w01.y, s0); fma2(a1[1], w01.y, s1);
                fma2(a0[2], w23.x, s0); fma2(a1[2], w23.x, s1);
                fma2(a0[3], w23.y, s0); fma2(a1[3], w23.y, s1);
                fma2(a0[4], w45.x, s0); fma2(a1[4], w45.x, s1);
                fma2(a0[5], w45.y, s0); fma2(a1[5], w45.y, s1);
            }
        }
        const int s0i = (NP == 2) ? 8 : 0;
#pragma unroll
        for (int j = 0; j < NP; ++j) {
            upk2(a0[j], xv0[s0i + 2 * j], xv0[s0i + 2 * j + 1]);
            upk2(a1[j], xv1[s0i + 2 * j], xv1[s0i + 2 * j + 1]);
        }
    }
#pragma unroll
    for (int s = 0; s < 12; ++s) {
        const bool isPN = (NP == 0) || (NP == 2 && s < 8);
        if (isPN) {
            int c = 12 * g + s;
            float w0 = sm[SM_WPN + 2 * c], w1 = sm[SM_WPN + 2 * c + 1];
            float bb = sm[SM_BPN + c];
            xv0[s] = fmaf(w0, pn00, fmaf(w1, pn10, bb));
            xv1[s] = fmaf(w0, pn01, fmaf(w1, pn11, bb));
        }
        float* cp = sm + SM_XC + s * 240 + p0;
        cp[0] = xv0[s] * m0;
        cp[1] = xv1[s] * m1;
    }
}

__global__ void __launch_bounds__(256, 2)
ffn_fused_kernel(const float* __restrict__ x,
                 const float* __restrict__ pneff,
                 const float* __restrict__ w_in,  const float* __restrict__ b_in,
                 const float* __restrict__ w_pn,  const float* __restrict__ b_pn,
                 const float* __restrict__ w_dw1, const float* __restrict__ b_dw1,
                 const float* __restrict__ w_dw3a,const float* __restrict__ b_dw3a,
                 const float* __restrict__ w_dw3b,const float* __restrict__ b_dw3b,
                 const float* __restrict__ w_out, const float* __restrict__ b_out,
                 float* __restrict__ out)
{
    extern __shared__ float sm[];
    const int tid = threadIdx.x;
    const int bx0 = blockIdx.x * 16;
    const int by0 = blockIdx.y * 8;
    const int b   = blockIdx.z;

    if (tid < 128) {
        sm[SM_BDW1 + tid]  = b_dw1[tid];
        sm[SM_BDW3A + tid] = b_dw3a[tid];
        sm[SM_BDW3B + tid] = b_dw3b[tid];
        sm[SM_BPN + tid]   = b_pn[tid];
    }
    if (tid < 64) sm[SM_BOUT + tid] = b_out[tid];
    sm[SM_WPN + tid] = w_pn[tid];
    sm[SM_BIN + tid] = b_in[tid];

    {
        const float* xb = x + (size_t)b * 64 * 65536;
        for (int v = tid; v < 64 * HALO; v += 256) {
            int c = v / HALO, p = v - c * HALO;
            int ry = p / 20, rx = p - ry * 20;
            int gy = by0 + ry - 2, gx = bx0 + rx - 2;
            float vv = 0.0f;
            if ((unsigned)gy < 256u && (unsigned)gx < 256u)
                vv = xb[(size_t)c * 65536 + gy * 256 + gx];
            sm[SM_SX + c * HALO + p] = vv;
        }
        const float* pnb = pneff + (size_t)b * 2 * 65536;
        for (int v = tid; v < 2 * HALO; v += 256) {
            int c = v / HALO, p = v - c * HALO;
            int ry = p / 20, rx = p - ry * 20;
            int gy = by0 + ry - 2, gx = bx0 + rx - 2;
            float vv = 0.0f;
            if ((unsigned)gy < 256u && (unsigned)gx < 256u)
                vv = pnb[(size_t)c * 65536 + gy * 256 + gx];
            sm[SM_SPN + c * HALO + p] = vv;
        }
    }
    __syncthreads();

    const int tA  = tid & 127;
    const int gh  = tid >> 7;
    const bool doA = (tA < 120);
    const int p0  = doA ? (2 * tA) : 0;      // adjacent pixel pair (p0, p0+1)
    float m0, m1;
    {
        int ry = p0 / 20, rx = p0 - ry * 20;
        m0 = ((unsigned)(by0 + ry - 2) < 256u && (unsigned)(bx0 + rx - 2) < 256u) ? 1.f : 0.f;
        int p1 = p0 + 1;
        int ry1 = p1 / 20, rx1 = p1 - ry1 * 20;
        m1 = ((unsigned)(by0 + ry1 - 2) < 256u && (unsigned)(bx0 + rx1 - 2) < 256u) ? 1.f : 0.f;
    }
    const float pn00 = sm[SM_SPN + p0],        pn01 = sm[SM_SPN + p0 + 1];
    const float pn10 = sm[SM_SPN + HALO + p0], pn11 = sm[SM_SPN + HALO + p0 + 1];

    const int tyl  = tA >> 4;
    const int tx   = tA & 15;
    const int warp = tid >> 5;
    const int lane = tid & 31;

    u64 acc[16];
#pragma unroll
    for (int i = 0; i < 16; ++i) acc[i] = 0ULL;

    for (int g = 0; g < 16; ++g) {
        // ---- stage per-group weights ----
        {
            const int nw = (g < 10) ? 768 : (g == 10 ? 1024 : 1536);
            const int ncol = nw / 64;
            for (int v = tid; v < nw; v += 256) {
                int k = v / ncol, j = v - k * ncol;
                int xi = (j < 12) ? (64 + 12 * g + j)
                                  : ((g == 10) ? (j - 12) : (12 * g - 128 + j - 12));
                sm[SM_WT + k * 24 + j] = w_in[xi * 64 + k];
            }
            for (int v = tid; v < 216; v += 256) {
                int cc = v / 27, t = v - cc * 27;
                int ch = 4 * g + (cc >> 1) + (cc & 1) * 64;
                sm[SM_GDW1 + cc * 28 + t]  = w_dw1[ch * 27 + t];
                sm[SM_GDW3A + cc * 28 + t] = w_dw3a[ch * 27 + t];
            }
            if (tid < 72) {
                int cc = tid / 9, t = tid - cc * 9;
                int ch = 4 * g + (cc >> 1) + (cc & 1) * 64;
                sm[SM_GDW3B + cc * 12 + t] = w_dw3b[ch * 9 + t];
            }
            {
                int cpl = tid >> 6, o = tid & 63;
                sm[SM_GWOUT + tid] = w_out[o * 64 + 4 * g + cpl];
            }
        }
        __syncthreads();   // weights ready

        // ---- Phase A (channel-split, packed pairs) ----
        if (gh == 0) {
            if (doA) phaseA_B(sm, g, p0, m0, m1);
        } else if (doA) {
            if (g < 10)       phaseA_A<0>(sm, g, p0, m0, m1, pn00, pn01, pn10, pn11);
            else if (g == 10) phaseA_A<2>(sm, g, p0, m0, m1, pn00, pn01, pn10, pn11);
            else              phaseA_A<6>(sm, g, p0, m0, m1, pn00, pn01, pn10, pn11);
        }
        __syncthreads();   // XC ready

        // ---- B1: warp = (cpl, chain), sliding window, raw d1 -> SM_D1 ----
        {
            const int cpl = warp >> 1, ch = warp & 1;
            const int cc = cpl * 2 + ch;
            float wr[28];
#pragma unroll
            for (int i = 0; i < 7; ++i) {
                float4 w4 = ((const float4*)(sm + SM_GDW1 + cc * 28))[i];
                wr[4 * i] = w4.x; wr[4 * i + 1] = w4.y;
                wr[4 * i + 2] = w4.z; wr[4 * i + 3] = w4.w;
            }
            const float bias = sm[SM_BDW1 + 4 * g + cpl + ch * 64];
            const float* xb = sm + SM_XC + (ch * 12 + 3 * cpl) * 240;
            float* dst = sm + SM_D1 + cc * 128;
            const bool ld = (lane < 18);
            float a0v[3], a1v[3], a2v[3], b0v[3], b1v[3], b2v[3], c0v[3], c1v[3], c2v[3];
#pragma unroll
            for (int j = 0; j < 3; ++j) {
                float v = ld ? xb[j * 240 + 20 + lane + 1] : 0.f;
                a0v[j] = v;
                a1v[j] = __shfl_down_sync(0xffffffffu, v, 1);
                a2v[j] = __shfl_down_sync(0xffffffffu, v, 2);
                float w = ld ? xb[j * 240 + 40 + lane + 1] : 0.f;
                b0v[j] = w;
                b1v[j] = __shfl_down_sync(0xffffffffu, w, 1);
                b2v[j] = __shfl_down_sync(0xffffffffu, w, 2);
            }
#pragma unroll
            for (int r = 0; r < 8; ++r) {
#pragma unroll
                for (int j = 0; j < 3; ++j) {
                    float v = ld ? xb[j * 240 + (r + 3) * 20 + lane + 1] : 0.f;
                    c0v[j] = v;
                    c1v[j] = __shfl_down_sync(0xffffffffu, v, 1);
                    c2v[j] = __shfl_down_sync(0xffffffffu, v, 2);
                }
                float d = bias;
#pragma unroll
                for (int j = 0; j < 3; ++j) {
                    d = fmaf(wr[j * 9 + 0], a0v[j], d);
                    d = fmaf(wr[j * 9 + 1], a1v[j], d);
                    d = fmaf(wr[j * 9 + 2], a2v[j], d);
                    d = fmaf(wr[j * 9 + 3], b0v[j], d);
                    d = fmaf(wr[j * 9 + 4], b1v[j], d);
                    d = fmaf(wr[j * 9 + 5], b2v[j], d);
                    d = fmaf(wr[j * 9 + 6], c0v[j], d);
                    d = fmaf(wr[j * 9 + 7], c1v[j], d);
                    d = fmaf(wr[j * 9 + 8], c2v[j], d);
                }
                if (lane < 16) dst[r * 16 + lane] = d;
#pragma unroll
                for (int j = 0; j < 3; ++j) {
                    a0v[j] = b0v[j]; a1v[j] = b1v[j]; a2v[j] = b2v[j];
                    b0v[j] = c0v[j]; b1v[j] = c1v[j]; b2v[j] = c2v[j];
                }
            }
        }

        // ---- B2: warp = (cpl, h), sliding window ----
        {
            const int cpl = warp >> 1, h = warp & 1;
            const int cc = cpl * 2 + h;
            const int cp = 4 * g + cpl;
            float wr[28];
#pragma unroll
            for (int i = 0; i < 7; ++i) {
                float4 w4 = ((const float4*)(sm + SM_GDW3A + cc * 28))[i];
                wr[4 * i] = w4.x; wr[4 * i + 1] = w4.y;
                wr[4 * i + 2] = w4.z; wr[4 * i + 3] = w4.w;
            }
            const float bias = sm[SM_BDW3A + cp + h * 64];
            const float* xb = sm + SM_XC + (h * 12 + 3 * cpl) * 240;
            float* dst = sm + SM_D3A + cpl * 360 + h * 180;
            const bool ld  = (lane < 20);
            const bool stv = (lane < 18);
            const int gxc  = bx0 + lane - 1;
            const bool colOK = stv && ((unsigned)gxc < 256u);

            float v0[3], v1[3], v2[3], p0v[3], p1v[3], p2v[3], r0[3], r1[3], r2[3];
#pragma unroll
            for (int j = 0; j < 3; ++j) {
                float a = ld ? xb[j * 240 + lane] : 0.0f;
                v0[j] = a;
                p0v[j] = __shfl_down_sync(0xffffffffu, a, 1);
                r0[j] = __shfl_down_sync(0xffffffffu, a, 2);
                float bva = ld ? xb[j * 240 + 20 + lane] : 0.0f;
                v1[j] = bva;
                p1v[j] = __shfl_down_sync(0xffffffffu, bva, 1);
                r1[j] = __shfl_down_sync(0xffffffffu, bva, 2);
            }
#pragma unroll
            for (int qy = 0; qy < 10; ++qy) {
#pragma unroll
                for (int j = 0; j < 3; ++j) {
                    float c = ld ? xb[j * 240 + (qy + 2) * 20 + lane] : 0.0f;
                    v2[j] = c;
                    p2v[j] = __shfl_down_sync(0xffffffffu, c, 1);
                    r2[j] = __shfl_down_sync(0xffffffffu, c, 2);
                }
                float d = bias;
#pragma unroll
                for (int j = 0; j < 3; ++j) {
                    d = fmaf(wr[j * 9 + 0], v0[j], d);
                    d = fmaf(wr[j * 9 + 1], p0v[j], d);
                    d = fmaf(wr[j * 9 + 2], r0[j], d);
                    d = fmaf(wr[j * 9 + 3], v1[j], d);
                    d = fmaf(wr[j * 9 + 4], p1v[j], d);
                    d = fmaf(wr[j * 9 + 5], r1[j], d);
                    d = fmaf(wr[j * 9 + 6], v2[j], d);
                    d = fmaf(wr[j * 9 + 7], p2v[j], d);
                    d = fmaf(wr[j * 9 + 8], r2[j], d);
                }
                if (stv) {
                    int gy = by0 + qy - 1;
                    bool ok = colOK && ((unsigned)gy < 256u);
                    dst[qy * 18 + lane] = ok ? d : 0.0f;
                }
#pragma unroll
                for (int j = 0; j < 3; ++j) {
                    v0[j] = v1[j]; p0v[j] = p1v[j]; r0[j] = r1[j];
                    v1[j] = v2[j]; p1v[j] = p2v[j]; r1[j] = r2[j];
                }
            }
        }
        __syncthreads();   // D1 + D3A ready

        if (gh == 0) {
            // ---- gating + packed proj (o 0..31) from D1 ----
#pragma unroll
            for (int cpl = 0; cpl < 4; ++cpl) {
                float d1a = sm[SM_D1 + (cpl * 2 + 0) * 128 + tA];
                float d1b = sm[SM_D1 + (cpl * 2 + 1) * 128 + tA];
                float g1 = gelu_exact(d1a) * d1b;
                u64 g1p = pk2(g1, g1);
                const ulonglong2* wo = (const ulonglong2*)(sm + SM_GWOUT + cpl * 64);
#pragma unroll
                for (int mm = 0; mm < 8; ++mm) {
                    ulonglong2 w2 = wo[mm];
                    fma2(acc[2 * mm], w2.x, g1p);
                    fma2(acc[2 * mm + 1], w2.y, g1p);
                }
            }
        } else {
            // ---- B3 + packed proj (o 32..63) ----
#pragma unroll
            for (int cpl = 0; cpl < 4; ++cpl) {
                const int cp = 4 * g + cpl;
                float wA[12], wB[12];
#pragma unroll
                for (int i = 0; i < 3; ++i) {
                    float4 w4 = ((const float4*)(sm + SM_GDW3B + (cpl * 2) * 12))[i];
                    wA[4 * i] = w4.x; wA[4 * i + 1] = w4.y;
                    wA[4 * i + 2] = w4.z; wA[4 * i + 3] = w4.w;
                    float4 v4 = ((const float4*)(sm + SM_GDW3B + (cpl * 2 + 1) * 12))[i];
                    wB[4 * i] = v4.x; wB[4 * i + 1] = v4.y;
                    wB[4 * i + 2] = v4.z; wB[4 * i + 3] = v4.w;
                }
                float dA = sm[SM_BDW3B + cp];
                float dB = sm[SM_BDW3B + cp + 64];
                const float* dz = sm + SM_D3A + cpl * 360;
#pragma unroll
                for (int ky = 0; ky < 3; ++ky)
#pragma unroll
                    for (int kx = 0; kx < 3; ++kx) {
                        int qi = (tyl + ky) * 18 + (tx + kx);
                        int t = ky * 3 + kx;
                        dA = fmaf(wA[t], dz[qi], dA);
                        dB = fmaf(wB[t], dz[180 + qi], dB);
                    }
                float g2 = gelu_exact(dA) * dB;
                u64 g2p = pk2(g2, g2);
                const ulonglong2* wo = (const ulonglong2*)(sm + SM_GWOUT + cpl * 64 + 32);
#pragma unroll
                for (int mm = 0; mm < 8; ++mm) {
                    ulonglong2 w2 = wo[mm];
                    fma2(acc[2 * mm], w2.x, g2p);
                    fma2(acc[2 * mm + 1], w2.y, g2p);
                }
            }
        }
        __syncthreads();   // protect WT/GDW*/XC/D1/D3A before next staging
    }

    float* ob = out + (size_t)b * 64 * 65536 + (size_t)(by0 + tyl) * 256 + (bx0 + tx);
    const int o0 = gh * 32;
#pragma unroll
    for (int mm = 0; mm < 16; ++mm) {
        float lo, hi;
        upk2(acc[mm], lo, hi);
        ob[(size_t)(o0 + 2 * mm) * 65536]     = lo + sm[SM_BOUT + o0 + 2 * mm];
        ob[(size_t)(o0 + 2 * mm + 1) * 65536] = hi + sm[SM_BOUT + o0 + 2 * mm + 1];
    }
}

extern "C" void kernel_launch(void* const* d_in, const int* in_sizes, int n_in,
                              void* d_out, int out_size)
{
    (void)in_sizes; (void)n_in; (void)out_size;
    const float* x      = (const float*)d_in[0];
    const float* pneff  = (const float*)d_in[1];
    const float* w_in   = (const float*)d_in[2];
    const float* b_in   = (const float*)d_in[3];
    const float* w_pn   = (const float*)d_in[4];
    const float* b_pn   = (const float*)d_in[5];
    const float* w_dw1  = (const float*)d_in[6];
    const float* b_dw1  = (const float*)d_in[7];
    const float* w_dw3a = (const float*)d_in[8];
    const float* b_dw3a = (const float*)d_in[9];
    const float* w_dw3b = (const float*)d_in[10];
    const float* b_dw3b = (const float*)d_in[11];
    const float* w_out  = (const float*)d_in[12];
    const float* b_out  = (const float*)d_in[13];
    float* out = (float*)d_out;

    const size_t smem_bytes = SM_TOTAL * sizeof(float);
    cudaFuncSetAttribute(ffn_fused_kernel,
                         cudaFuncAttributeMaxDynamicSharedMemorySize,
                         (int)smem_bytes);
    dim3 grid(16, 32, 4);
    ffn_fused_kernel<<<grid, 256, smem_bytes>>>(
        x, pneff, w_in, b_in, w_pn, b_pn, w_dw1, b_dw1,
        w_dw3a, b_dw3a, w_dw3b, b_dw3b, w_out, b_out, out);
}